// round 4
// baseline (speedup 1.0000x reference)
#include <cuda_runtime.h>
#include <math.h>
#include <math_constants.h>

// Problem constants (fixed by the dataset)
#define N_NODES 100000
#define N_EDGES 1600000
#define F_IN    128
#define F_HID   128
#define F_OUT   40
#define F_OUT_P 64   // padded layer-3 width

// ---------------- device scratch (no allocations allowed) ----------------
__device__ int   d_deg[N_NODES];
__device__ int   d_off[N_NODES + 1];
__device__ int   d_cur[N_NODES];
__device__ int   d_csrc[N_EDGES];
__device__ float d_agg[(size_t)N_NODES * F_HID];
__device__ float d_h[(size_t)N_NODES * F_HID];
__device__ float d_hn3[(size_t)N_NODES * F_OUT_P];
__device__ float d_Wc1[256 * F_HID];
__device__ float d_Wc2[256 * F_HID];
__device__ float d_Ws3p[128 * F_OUT_P];
__device__ float d_Wn3p[128 * F_OUT_P];
__device__ float d_bc1[F_HID];
__device__ float d_bc2[F_HID];
__device__ float d_bc3[F_OUT_P];

// ---------------- CSR construction ----------------
__global__ void zero_deg_kernel() {
    int i = blockIdx.x * blockDim.x + threadIdx.x;
    if (i < N_NODES) d_deg[i] = 0;
}

__global__ void hist_kernel(const int* __restrict__ dst) {
    int e = blockIdx.x * blockDim.x + threadIdx.x;
    if (e < N_EDGES) atomicAdd(&d_deg[dst[e]], 1);
}

// single-block exclusive scan over degrees -> offsets (warp-shuffle based)
__global__ void scan_kernel() {
    __shared__ int s_w[32];
    __shared__ int carry_s;
    int tid = threadIdx.x;
    int lane = tid & 31, wid = tid >> 5;
    if (tid == 0) { d_off[0] = 0; carry_s = 0; }
    __syncthreads();
    for (int base = 0; base < N_NODES; base += 1024) {
        int idx = base + tid;
        int x = (idx < N_NODES) ? d_deg[idx] : 0;
        #pragma unroll
        for (int o = 1; o < 32; o <<= 1) {
            int t = __shfl_up_sync(0xffffffffu, x, o);
            if (lane >= o) x += t;
        }
        if (lane == 31) s_w[wid] = x;
        __syncthreads();
        if (wid == 0) {
            int s = s_w[lane];
            #pragma unroll
            for (int o = 1; o < 32; o <<= 1) {
                int t = __shfl_up_sync(0xffffffffu, s, o);
                if (lane >= o) s += t;
            }
            s_w[lane] = s;
        }
        __syncthreads();
        int incl = x + (wid ? s_w[wid - 1] : 0);
        int carry = carry_s;
        if (idx < N_NODES) d_off[idx + 1] = carry + incl;
        __syncthreads();
        if (tid == 0) carry_s = carry + s_w[31];
        __syncthreads();
    }
}

__global__ void copy_cursor_kernel() {
    int i = blockIdx.x * blockDim.x + threadIdx.x;
    if (i < N_NODES) d_cur[i] = d_off[i];
}

__global__ void fill_kernel(const int* __restrict__ src, const int* __restrict__ dst) {
    int e = blockIdx.x * blockDim.x + threadIdx.x;
    if (e < N_EDGES) {
        int pos = atomicAdd(&d_cur[dst[e]], 1);
        d_csrc[pos] = src[e];
    }
}

// ---------------- mean aggregation (128-wide): one warp per node, 4-wide MLP ----------------
__global__ void agg_kernel(const float* __restrict__ xin, float* __restrict__ agg) {
    int w = (blockIdx.x * blockDim.x + threadIdx.x) >> 5;
    int lane = threadIdx.x & 31;
    if (w >= N_NODES) return;
    int s0 = d_off[w], s1 = d_off[w + 1];
    float4 acc = make_float4(0.f, 0.f, 0.f, 0.f);
    const float4* xv = (const float4*)xin;
    int j = s0;
    for (; j + 3 < s1; j += 4) {
        int a = d_csrc[j], b = d_csrc[j + 1], c = d_csrc[j + 2], d = d_csrc[j + 3];
        float4 va = xv[(size_t)a * 32 + lane];
        float4 vb = xv[(size_t)b * 32 + lane];
        float4 vc = xv[(size_t)c * 32 + lane];
        float4 vd = xv[(size_t)d * 32 + lane];
        acc.x += (va.x + vb.x) + (vc.x + vd.x);
        acc.y += (va.y + vb.y) + (vc.y + vd.y);
        acc.z += (va.z + vb.z) + (vc.z + vd.z);
        acc.w += (va.w + vb.w) + (vc.w + vd.w);
    }
    for (; j < s1; j++) {
        int a = d_csrc[j];
        float4 va = xv[(size_t)a * 32 + lane];
        acc.x += va.x; acc.y += va.y; acc.z += va.z; acc.w += va.w;
    }
    float inv = 1.0f / fmaxf((float)(s1 - s0), 1.0f);
    acc.x *= inv; acc.y *= inv; acc.z *= inv; acc.w *= inv;
    ((float4*)agg)[(size_t)w * 32 + lane] = acc;
}

// ---------------- mean aggregation (64-wide): one warp per node, float2/lane ----------------
__global__ void agg64_kernel(const float* __restrict__ xin, float* __restrict__ agg) {
    int w = (blockIdx.x * blockDim.x + threadIdx.x) >> 5;
    int lane = threadIdx.x & 31;
    if (w >= N_NODES) return;
    int s0 = d_off[w], s1 = d_off[w + 1];
    float2 acc = make_float2(0.f, 0.f);
    const float2* xv = (const float2*)xin;
    int j = s0;
    for (; j + 3 < s1; j += 4) {
        int a = d_csrc[j], b = d_csrc[j + 1], c = d_csrc[j + 2], d = d_csrc[j + 3];
        float2 va = xv[(size_t)a * 32 + lane];
        float2 vb = xv[(size_t)b * 32 + lane];
        float2 vc = xv[(size_t)c * 32 + lane];
        float2 vd = xv[(size_t)d * 32 + lane];
        acc.x += (va.x + vb.x) + (vc.x + vd.x);
        acc.y += (va.y + vb.y) + (vc.y + vd.y);
    }
    for (; j < s1; j++) {
        int a = d_csrc[j];
        float2 va = xv[(size_t)a * 32 + lane];
        acc.x += va.x; acc.y += va.y;
    }
    float inv = 1.0f / fmaxf((float)(s1 - s0), 1.0f);
    acc.x *= inv; acc.y *= inv;
    ((float2*)agg)[(size_t)w * 32 + lane] = acc;
}

// ---------------- weight prep: concat [Ws;Wn], fold BN (layers 1/2) ----------------
__global__ void prep_w_kernel(const float* __restrict__ Ws, const float* __restrict__ Wn,
                              const float* __restrict__ b,
                              const float* __restrict__ g, const float* __restrict__ be,
                              const float* __restrict__ m, const float* __restrict__ v,
                              float* __restrict__ Wc, float* __restrict__ bc) {
    int id = blockIdx.x * blockDim.x + threadIdx.x;
    if (id >= 256 * 128) return;
    int k = id >> 7, c = id & 127;
    float s = g[c] * rsqrtf(v[c] + 1e-5f);
    float t = be[c] - m[c] * s;
    float w = (k < 128) ? Ws[k * 128 + c] : Wn[(k - 128) * 128 + c];
    Wc[id] = w * s;
    if (k == 0) bc[c] = b[c] * s + t;
}

// ---------------- weight prep layer 3: pad 40->64 cols, separate Ws/Wn ----------------
__global__ void prep_w3_kernel(const float* __restrict__ Ws, const float* __restrict__ Wn,
                               const float* __restrict__ b,
                               float* __restrict__ Wsp, float* __restrict__ Wnp,
                               float* __restrict__ bc) {
    int id = blockIdx.x * blockDim.x + threadIdx.x;
    if (id >= 128 * F_OUT_P) return;
    int k = id >> 6, c = id & 63;
    float ws = 0.f, wn = 0.f;
    if (c < F_OUT) { ws = Ws[k * F_OUT + c]; wn = Wn[k * F_OUT + c]; }
    Wsp[id] = ws;
    Wnp[id] = wn;
    if (k == 0) bc[c] = (c < F_OUT) ? b[c] : 0.f;
}

// ---------------- fused GEMM (layers 1/2): out = [X|Agg] @ W + bias, ReLU ----------------
// BM=64 rows/block, K=256 resident A-tile, BK=64 weight chunks, 256 threads.
__global__ void __launch_bounds__(256, 2) gemm256_kernel(
        const float* __restrict__ X, const float* __restrict__ Agg,
        const float* __restrict__ W, const float* __restrict__ bias,
        float* __restrict__ out) {
    constexpr int BM = 64, TM = 8, BK = 64, BN = 128, TN = 4;
    extern __shared__ float smem[];
    float* As = smem;                 // [BM][256]
    float* Bs = smem + BM * 256;      // [BK][BN]

    int tid = threadIdx.x;
    int row0 = blockIdx.x * BM;
    int tx = tid & 31;
    int ty = tid >> 5;

    // Load A tile: BM x 256 floats = 4096 float4, 16 per thread.
    #pragma unroll
    for (int i = 0; i < 16; i++) {
        int idx = tid + i * 256;
        int r = idx >> 6;
        int c4 = idx & 63;
        int gr = row0 + r;
        float4 vv = make_float4(0.f, 0.f, 0.f, 0.f);
        if (gr < N_NODES) {
            vv = (c4 < 32)
                ? ((const float4*)(X   + (size_t)gr * 128))[c4]
                : ((const float4*)(Agg + (size_t)gr * 128))[c4 - 32];
        }
        ((float4*)As)[idx] = vv;
    }

    float acc[TM][TN];
    #pragma unroll
    for (int i = 0; i < TM; i++)
        #pragma unroll
        for (int j = 0; j < TN; j++) acc[i][j] = 0.f;

    #pragma unroll 1
    for (int kc = 0; kc < 4; kc++) {
        __syncthreads();
        #pragma unroll
        for (int i = 0; i < (BK * BN) / (4 * 256); i++) {
            int idx = tid + i * 256;
            ((float4*)Bs)[idx] = ((const float4*)(W + (size_t)kc * BK * BN))[idx];
        }
        __syncthreads();

        const float* a0 = As + (ty * TM) * 256 + kc * BK;
        #pragma unroll 2
        for (int k = 0; k < BK; k += 4) {
            float4 a[TM];
            #pragma unroll
            for (int i = 0; i < TM; i++)
                a[i] = *(const float4*)(a0 + i * 256 + k);
            #pragma unroll
            for (int kk = 0; kk < 4; kk++) {
                float4 b = *(const float4*)(Bs + (k + kk) * BN + tx * TN);
                #pragma unroll
                for (int i = 0; i < TM; i++) {
                    float av = (kk == 0) ? a[i].x : (kk == 1) ? a[i].y
                             : (kk == 2) ? a[i].z : a[i].w;
                    acc[i][0] = fmaf(av, b.x, acc[i][0]);
                    acc[i][1] = fmaf(av, b.y, acc[i][1]);
                    acc[i][2] = fmaf(av, b.z, acc[i][2]);
                    acc[i][3] = fmaf(av, b.w, acc[i][3]);
                }
            }
        }
    }

    #pragma unroll
    for (int i = 0; i < TM; i++) {
        int gr = row0 + ty * TM + i;
        if (gr < N_NODES) {
            float4 v;
            v.x = fmaxf(acc[i][0] + bias[tx * TN + 0], 0.f);
            v.y = fmaxf(acc[i][1] + bias[tx * TN + 1], 0.f);
            v.z = fmaxf(acc[i][2] + bias[tx * TN + 2], 0.f);
            v.w = fmaxf(acc[i][3] + bias[tx * TN + 3], 0.f);
            *(float4*)(out + (size_t)gr * 128 + tx * TN) = v;
        }
    }
}

// ---------------- K=128 GEMM body (shared by layer-3 kernels) ----------------
// BM=64, K=128 A-tile resident, BN=64, TM=8, TN=2, 256 threads, single BK=128 chunk.
// Each warp (ty) owns TM full rows; lane tx holds cols {2tx, 2tx+1}.
__device__ __forceinline__ void gemm128_body(
        const float* __restrict__ X, const float* __restrict__ W,
        float (&acc)[8][2], float* As, float* Bs, int row0) {
    constexpr int TM = 8, BN = 64;
    int tid = threadIdx.x;
    int tx = tid & 31;
    int ty = tid >> 5;

    // Load A tile: 64 x 128 floats = 2048 float4, 8 per thread.
    #pragma unroll
    for (int i = 0; i < 8; i++) {
        int idx = tid + i * 256;
        int r = idx >> 5;             // /32 float4 per row
        int c4 = idx & 31;
        int gr = row0 + r;
        float4 vv = make_float4(0.f, 0.f, 0.f, 0.f);
        if (gr < N_NODES) vv = ((const float4*)(X + (size_t)gr * 128))[c4];
        ((float4*)As)[idx] = vv;
    }
    // Load W: 128 x 64 floats = 2048 float4, 8 per thread.
    #pragma unroll
    for (int i = 0; i < 8; i++) {
        int idx = tid + i * 256;
        ((float4*)Bs)[idx] = ((const float4*)W)[idx];
    }
    __syncthreads();

    const float* a0 = As + (ty * TM) * 128;
    #pragma unroll 2
    for (int k = 0; k < 128; k += 4) {
        float4 a[TM];
        #pragma unroll
        for (int i = 0; i < TM; i++)
            a[i] = *(const float4*)(a0 + i * 128 + k);
        #pragma unroll
        for (int kk = 0; kk < 4; kk++) {
            float2 b = *(const float2*)(Bs + (k + kk) * BN + tx * 2);
            #pragma unroll
            for (int i = 0; i < TM; i++) {
                float av = (kk == 0) ? a[i].x : (kk == 1) ? a[i].y
                         : (kk == 2) ? a[i].z : a[i].w;
                acc[i][0] = fmaf(av, b.x, acc[i][0]);
                acc[i][1] = fmaf(av, b.y, acc[i][1]);
            }
        }
    }
}

// layer-3 neighbor GEMM: hn3 = h2 @ Wn3p  (N x 64, padded cols are exact zero)
__global__ void __launch_bounds__(256) gemm_n3_kernel(
        const float* __restrict__ X, const float* __restrict__ W,
        float* __restrict__ out) {
    extern __shared__ float smem[];
    float* As = smem;             // [64][128]
    float* Bs = smem + 64 * 128;  // [128][64]
    int row0 = blockIdx.x * 64;
    int tx = threadIdx.x & 31, ty = threadIdx.x >> 5;
    float acc[8][2];
    #pragma unroll
    for (int i = 0; i < 8; i++) { acc[i][0] = 0.f; acc[i][1] = 0.f; }
    gemm128_body(X, W, acc, As, Bs, row0);
    #pragma unroll
    for (int i = 0; i < 8; i++) {
        int gr = row0 + ty * 8 + i;
        if (gr < N_NODES)
            *(float2*)(out + (size_t)gr * 64 + tx * 2) = make_float2(acc[i][0], acc[i][1]);
    }
}

// layer-3 self GEMM + agg + bias + fused log_softmax -> out (N x 40)
__global__ void __launch_bounds__(256) gemm_s3_lsm_kernel(
        const float* __restrict__ X, const float* __restrict__ W,
        const float* __restrict__ Agg, const float* __restrict__ bias,
        float* __restrict__ out) {
    extern __shared__ float smem[];
    float* As = smem;
    float* Bs = smem + 64 * 128;
    int row0 = blockIdx.x * 64;
    int tx = threadIdx.x & 31, ty = threadIdx.x >> 5;
    float acc[8][2];
    #pragma unroll
    for (int i = 0; i < 8; i++) { acc[i][0] = 0.f; acc[i][1] = 0.f; }
    gemm128_body(X, W, acc, As, Bs, row0);

    float2 bv = *(const float2*)(bias + tx * 2);
    bool valid = (tx < 20);   // cols 2tx, 2tx+1 < 40
    #pragma unroll
    for (int i = 0; i < 8; i++) {
        int gr = row0 + ty * 8 + i;
        if (gr < N_NODES) {
            float2 ag = *(const float2*)(Agg + (size_t)gr * 64 + tx * 2);
            float v0 = acc[i][0] + ag.x + bv.x;
            float v1 = acc[i][1] + ag.y + bv.y;
            float m0 = valid ? v0 : -CUDART_INF_F;
            float m1 = valid ? v1 : -CUDART_INF_F;
            float mx = fmaxf(m0, m1);
            #pragma unroll
            for (int o = 16; o; o >>= 1)
                mx = fmaxf(mx, __shfl_xor_sync(0xffffffffu, mx, o));
            float e = __expf(m0 - mx) + __expf(m1 - mx);  // exp(-inf)=0
            #pragma unroll
            for (int o = 16; o; o >>= 1)
                e += __shfl_xor_sync(0xffffffffu, e, o);
            float ls = mx + __logf(e);
            if (valid)
                *(float2*)(out + (size_t)gr * F_OUT + tx * 2) =
                    make_float2(v0 - ls, v1 - ls);
        }
    }
}

// ---------------- host launcher ----------------
extern "C" void kernel_launch(void* const* d_in, const int* in_sizes, int n_in,
                              void* d_out, int out_size) {
    const float* x   = (const float*)d_in[0];
    const int*   ei  = (const int*)d_in[1];
    const float* Ws1 = (const float*)d_in[2];
    const float* Wn1 = (const float*)d_in[3];
    const float* b1  = (const float*)d_in[4];
    const float* Ws2 = (const float*)d_in[5];
    const float* Wn2 = (const float*)d_in[6];
    const float* b2  = (const float*)d_in[7];
    const float* Ws3 = (const float*)d_in[8];
    const float* Wn3 = (const float*)d_in[9];
    const float* b3  = (const float*)d_in[10];
    const float* g1  = (const float*)d_in[11];
    const float* be1 = (const float*)d_in[12];
    const float* m1  = (const float*)d_in[13];
    const float* v1  = (const float*)d_in[14];
    const float* g2  = (const float*)d_in[15];
    const float* be2 = (const float*)d_in[16];
    const float* m2  = (const float*)d_in[17];
    const float* v2  = (const float*)d_in[18];
    float* out = (float*)d_out;

    const int* e_src = ei;
    const int* e_dst = ei + N_EDGES;

    float *p_agg, *p_h, *p_hn3, *p_Wc1, *p_Wc2, *p_Ws3p, *p_Wn3p, *p_bc1, *p_bc2, *p_bc3;
    cudaGetSymbolAddress((void**)&p_agg,  d_agg);
    cudaGetSymbolAddress((void**)&p_h,    d_h);
    cudaGetSymbolAddress((void**)&p_hn3,  d_hn3);
    cudaGetSymbolAddress((void**)&p_Wc1,  d_Wc1);
    cudaGetSymbolAddress((void**)&p_Wc2,  d_Wc2);
    cudaGetSymbolAddress((void**)&p_Ws3p, d_Ws3p);
    cudaGetSymbolAddress((void**)&p_Wn3p, d_Wn3p);
    cudaGetSymbolAddress((void**)&p_bc1,  d_bc1);
    cudaGetSymbolAddress((void**)&p_bc2,  d_bc2);
    cudaGetSymbolAddress((void**)&p_bc3,  d_bc3);

    const int NB_N    = (N_NODES + 255) / 256;        // 391
    const int NB_E    = (N_EDGES + 255) / 256;        // 6250
    const int NB_WARP = (N_NODES * 32 + 255) / 256;   // 12500
    const int NB_GEMM = (N_NODES + 63) / 64;          // 1563

    const size_t smem256 = (64 * 256 + 64 * 128) * sizeof(float); // 96 KB
    const size_t smem128 = (64 * 128 + 128 * 64) * sizeof(float); // 64 KB
    cudaFuncSetAttribute(gemm256_kernel, cudaFuncAttributeMaxDynamicSharedMemorySize, (int)smem256);
    cudaFuncSetAttribute(gemm_n3_kernel, cudaFuncAttributeMaxDynamicSharedMemorySize, (int)smem128);
    cudaFuncSetAttribute(gemm_s3_lsm_kernel, cudaFuncAttributeMaxDynamicSharedMemorySize, (int)smem128);

    // CSR build
    zero_deg_kernel<<<NB_N, 256>>>();
    hist_kernel<<<NB_E, 256>>>(e_dst);
    scan_kernel<<<1, 1024>>>();
    copy_cursor_kernel<<<NB_N, 256>>>();
    fill_kernel<<<NB_E, 256>>>(e_src, e_dst);

    // weight prep
    prep_w_kernel<<<(256 * 128 + 255) / 256, 256>>>(Ws1, Wn1, b1, g1, be1, m1, v1, p_Wc1, p_bc1);
    prep_w_kernel<<<(256 * 128 + 255) / 256, 256>>>(Ws2, Wn2, b2, g2, be2, m2, v2, p_Wc2, p_bc2);
    prep_w3_kernel<<<(128 * F_OUT_P + 255) / 256, 256>>>(Ws3, Wn3, b3, p_Ws3p, p_Wn3p, p_bc3);

    // layer 1
    agg_kernel<<<NB_WARP, 256>>>(x, p_agg);
    gemm256_kernel<<<NB_GEMM, 256, smem256>>>(x, p_agg, p_Wc1, p_bc1, p_h);
    // layer 2 (in place: each block reads/writes only its own rows)
    agg_kernel<<<NB_WARP, 256>>>(p_h, p_agg);
    gemm256_kernel<<<NB_GEMM, 256, smem256>>>(p_h, p_agg, p_Wc2, p_bc2, p_h);
    // layer 3: neighbor GEMM first (agg is linear), then 64-wide agg, then
    // self GEMM + agg + bias + fused log_softmax
    gemm_n3_kernel<<<NB_GEMM, 256, smem128>>>(p_h, p_Wn3p, p_hn3);
    agg64_kernel<<<NB_WARP, 256>>>(p_hn3, p_agg);
    gemm_s3_lsm_kernel<<<NB_GEMM, 256, smem128>>>(p_h, p_Ws3p, p_agg, p_bc3, out);
}

// round 12
// speedup vs baseline: 1.4350x; 1.4350x over previous
#include <cuda_runtime.h>
#include <math.h>
#include <math_constants.h>

// Problem constants (fixed by the dataset)
#define N_NODES 100000
#define N_EDGES 1600000
#define F_IN    128
#define F_HID   128
#define F_OUT   40
#define F_OUT_P 64   // padded layer-3 width

// ---------------- device scratch (no allocations allowed) ----------------
__device__ int   d_deg[N_NODES];
__device__ int   d_off[N_NODES + 1];
__device__ int   d_cur[N_NODES];
__device__ int   d_csrc[N_EDGES];
__device__ float d_agg[(size_t)N_NODES * F_HID];
__device__ float d_h[(size_t)N_NODES * F_HID];
__device__ float d_hn3[(size_t)N_NODES * F_OUT_P];
__device__ float d_Wc1[256 * F_HID];
__device__ float d_Wc2[256 * F_HID];
__device__ float d_Ws3p[128 * F_OUT_P];
__device__ float d_Wn3p[128 * F_OUT_P];
__device__ float d_bc1[F_HID];
__device__ float d_bc2[F_HID];
__device__ float d_bc3[F_OUT_P];

// ---------------- CSR construction ----------------
__global__ void zero_deg_kernel() {
    int i = blockIdx.x * blockDim.x + threadIdx.x;
    if (i < N_NODES) d_deg[i] = 0;
}

__global__ void hist_kernel(const int* __restrict__ dst) {
    int e = blockIdx.x * blockDim.x + threadIdx.x;
    if (e < N_EDGES) atomicAdd(&d_deg[dst[e]], 1);
}

// single-block exclusive scan over degrees -> offsets (warp-shuffle based)
__global__ void scan_kernel() {
    __shared__ int s_w[32];
    __shared__ int carry_s;
    int tid = threadIdx.x;
    int lane = tid & 31, wid = tid >> 5;
    if (tid == 0) { d_off[0] = 0; carry_s = 0; }
    __syncthreads();
    for (int base = 0; base < N_NODES; base += 1024) {
        int idx = base + tid;
        int x = (idx < N_NODES) ? d_deg[idx] : 0;
        #pragma unroll
        for (int o = 1; o < 32; o <<= 1) {
            int t = __shfl_up_sync(0xffffffffu, x, o);
            if (lane >= o) x += t;
        }
        if (lane == 31) s_w[wid] = x;
        __syncthreads();
        if (wid == 0) {
            int s = s_w[lane];
            #pragma unroll
            for (int o = 1; o < 32; o <<= 1) {
                int t = __shfl_up_sync(0xffffffffu, s, o);
                if (lane >= o) s += t;
            }
            s_w[lane] = s;
        }
        __syncthreads();
        int incl = x + (wid ? s_w[wid - 1] : 0);
        int carry = carry_s;
        if (idx < N_NODES) d_off[idx + 1] = carry + incl;
        __syncthreads();
        if (tid == 0) carry_s = carry + s_w[31];
        __syncthreads();
    }
}

__global__ void copy_cursor_kernel() {
    int i = blockIdx.x * blockDim.x + threadIdx.x;
    if (i < N_NODES) d_cur[i] = d_off[i];
}

__global__ void fill_kernel(const int* __restrict__ src, const int* __restrict__ dst) {
    int e = blockIdx.x * blockDim.x + threadIdx.x;
    if (e < N_EDGES) {
        int pos = atomicAdd(&d_cur[dst[e]], 1);
        d_csrc[pos] = src[e];
    }
}

// ---------------- mean aggregation (128-wide): one warp per node, 4-wide MLP ----------------
__global__ void agg_kernel(const float* __restrict__ xin, float* __restrict__ agg) {
    int w = (blockIdx.x * blockDim.x + threadIdx.x) >> 5;
    int lane = threadIdx.x & 31;
    if (w >= N_NODES) return;
    int s0 = d_off[w], s1 = d_off[w + 1];
    float4 acc = make_float4(0.f, 0.f, 0.f, 0.f);
    const float4* xv = (const float4*)xin;
    int j = s0;
    for (; j + 3 < s1; j += 4) {
        int a = d_csrc[j], b = d_csrc[j + 1], c = d_csrc[j + 2], d = d_csrc[j + 3];
        float4 va = xv[(size_t)a * 32 + lane];
        float4 vb = xv[(size_t)b * 32 + lane];
        float4 vc = xv[(size_t)c * 32 + lane];
        float4 vd = xv[(size_t)d * 32 + lane];
        acc.x += (va.x + vb.x) + (vc.x + vd.x);
        acc.y += (va.y + vb.y) + (vc.y + vd.y);
        acc.z += (va.z + vb.z) + (vc.z + vd.z);
        acc.w += (va.w + vb.w) + (vc.w + vd.w);
    }
    for (; j < s1; j++) {
        int a = d_csrc[j];
        float4 va = xv[(size_t)a * 32 + lane];
        acc.x += va.x; acc.y += va.y; acc.z += va.z; acc.w += va.w;
    }
    float inv = 1.0f / fmaxf((float)(s1 - s0), 1.0f);
    acc.x *= inv; acc.y *= inv; acc.z *= inv; acc.w *= inv;
    ((float4*)agg)[(size_t)w * 32 + lane] = acc;
}

// ---------------- mean aggregation (64-wide): one warp per node, float2/lane ----------------
__global__ void agg64_kernel(const float* __restrict__ xin, float* __restrict__ agg) {
    int w = (blockIdx.x * blockDim.x + threadIdx.x) >> 5;
    int lane = threadIdx.x & 31;
    if (w >= N_NODES) return;
    int s0 = d_off[w], s1 = d_off[w + 1];
    float2 acc = make_float2(0.f, 0.f);
    const float2* xv = (const float2*)xin;
    int j = s0;
    for (; j + 3 < s1; j += 4) {
        int a = d_csrc[j], b = d_csrc[j + 1], c = d_csrc[j + 2], d = d_csrc[j + 3];
        float2 va = xv[(size_t)a * 32 + lane];
        float2 vb = xv[(size_t)b * 32 + lane];
        float2 vc = xv[(size_t)c * 32 + lane];
        float2 vd = xv[(size_t)d * 32 + lane];
        acc.x += (va.x + vb.x) + (vc.x + vd.x);
        acc.y += (va.y + vb.y) + (vc.y + vd.y);
    }
    for (; j < s1; j++) {
        int a = d_csrc[j];
        float2 va = xv[(size_t)a * 32 + lane];
        acc.x += va.x; acc.y += va.y;
    }
    float inv = 1.0f / fmaxf((float)(s1 - s0), 1.0f);
    acc.x *= inv; acc.y *= inv;
    ((float2*)agg)[(size_t)w * 32 + lane] = acc;
}

// ---------------- weight prep: concat [Ws;Wn], fold BN (layers 1/2) ----------------
__global__ void prep_w_kernel(const float* __restrict__ Ws, const float* __restrict__ Wn,
                              const float* __restrict__ b,
                              const float* __restrict__ g, const float* __restrict__ be,
                              const float* __restrict__ m, const float* __restrict__ v,
                              float* __restrict__ Wc, float* __restrict__ bc) {
    int id = blockIdx.x * blockDim.x + threadIdx.x;
    if (id >= 256 * 128) return;
    int k = id >> 7, c = id & 127;
    float s = g[c] * rsqrtf(v[c] + 1e-5f);
    float t = be[c] - m[c] * s;
    float w = (k < 128) ? Ws[k * 128 + c] : Wn[(k - 128) * 128 + c];
    Wc[id] = w * s;
    if (k == 0) bc[c] = b[c] * s + t;
}

// ---------------- weight prep layer 3: pad 40->64 cols, separate Ws/Wn ----------------
__global__ void prep_w3_kernel(const float* __restrict__ Ws, const float* __restrict__ Wn,
                               const float* __restrict__ b,
                               float* __restrict__ Wsp, float* __restrict__ Wnp,
                               float* __restrict__ bc) {
    int id = blockIdx.x * blockDim.x + threadIdx.x;
    if (id >= 128 * F_OUT_P) return;
    int k = id >> 6, c = id & 63;
    float ws = 0.f, wn = 0.f;
    if (c < F_OUT) { ws = Ws[k * F_OUT + c]; wn = Wn[k * F_OUT + c]; }
    Wsp[id] = ws;
    Wnp[id] = wn;
    if (k == 0) bc[c] = (c < F_OUT) ? b[c] : 0.f;
}

// ---------------- TF32 helpers ----------------
__device__ __forceinline__ unsigned f2tf32(float f) {
    unsigned u;
    asm("cvt.rna.tf32.f32 %0, %1;" : "=r"(u) : "f"(f));
    return u;
}

__device__ __forceinline__ void mma_tf32(float& c0, float& c1, float& c2, float& c3,
                                         unsigned a0, unsigned a1, unsigned a2, unsigned a3,
                                         unsigned b0, unsigned b1) {
    asm volatile(
        "mma.sync.aligned.m16n8k8.row.col.f32.tf32.tf32.f32 "
        "{%0,%1,%2,%3}, {%4,%5,%6,%7}, {%8,%9}, {%0,%1,%2,%3};"
        : "+f"(c0), "+f"(c1), "+f"(c2), "+f"(c3)
        : "r"(a0), "r"(a1), "r"(a2), "r"(a3), "r"(b0), "r"(b1));
}

// ---------------- layers 1/2 GEMM via TF32 mma.sync ----------------
// C[N x 128] = [X|Agg][N x 256] @ W[256 x 128] + bias, ReLU.
// CTA: BM=64 rows, BN=128 cols, 256 threads = 8 warps (4 along M x 2 along N).
// As stride 260: frag bank=(4fr+fc)&31 conflict-free. Bs stride 136: (8fc+fr)&31.
#define AS_LD 260
#define BS_LD 136
__global__ void __launch_bounds__(256, 2) gemm_tf32_kernel(
        const float* __restrict__ X, const float* __restrict__ Agg,
        const float* __restrict__ W, const float* __restrict__ bias,
        float* __restrict__ out) {
    extern __shared__ float smem[];
    float* As = smem;                       // [64][AS_LD]
    float* Bs = smem + 64 * AS_LD;          // [64][BS_LD] per chunk

    int tid = threadIdx.x;
    int lane = tid & 31;
    int wid = tid >> 5;
    int warp_m = wid & 3;
    int warp_n = wid >> 2;
    int row0 = blockIdx.x * 64;

    #pragma unroll
    for (int i = 0; i < 16; i++) {
        int idx = tid + i * 256;
        int r = idx >> 6;
        int c4 = idx & 63;
        int gr = row0 + r;
        float4 vv = make_float4(0.f, 0.f, 0.f, 0.f);
        if (gr < N_NODES) {
            vv = (c4 < 32)
                ? ((const float4*)(X   + (size_t)gr * 128))[c4]
                : ((const float4*)(Agg + (size_t)gr * 128))[c4 - 32];
        }
        unsigned* dstp = (unsigned*)(As + r * AS_LD + c4 * 4);
        dstp[0] = f2tf32(vv.x); dstp[1] = f2tf32(vv.y);
        dstp[2] = f2tf32(vv.z); dstp[3] = f2tf32(vv.w);
    }

    float acc[8][4];
    #pragma unroll
    for (int i = 0; i < 8; i++)
        #pragma unroll
        for (int j = 0; j < 4; j++) acc[i][j] = 0.f;

    int fr = lane >> 2;
    int fc = lane & 3;
    const unsigned* Asu = (const unsigned*)As;
    const unsigned* Bsu = (const unsigned*)Bs;

    #pragma unroll 1
    for (int kc = 0; kc < 4; kc++) {
        __syncthreads();
        #pragma unroll
        for (int i = 0; i < 8; i++) {
            int idx = tid + i * 256;
            int k = idx >> 5;
            int c4 = idx & 31;
            float4 vv = ((const float4*)(W + (size_t)(kc * 64 + k) * 128))[c4];
            unsigned* dstp = (unsigned*)(Bs + k * BS_LD + c4 * 4);
            dstp[0] = f2tf32(vv.x); dstp[1] = f2tf32(vv.y);
            dstp[2] = f2tf32(vv.z); dstp[3] = f2tf32(vv.w);
        }
        __syncthreads();

        #pragma unroll
        for (int k8 = 0; k8 < 8; k8++) {
            int kk = kc * 64 + k8 * 8;
            int arow = warp_m * 16 + fr;
            unsigned a0 = Asu[arow * AS_LD + kk + fc];
            unsigned a1 = Asu[(arow + 8) * AS_LD + kk + fc];
            unsigned a2 = Asu[arow * AS_LD + kk + fc + 4];
            unsigned a3 = Asu[(arow + 8) * AS_LD + kk + fc + 4];
            int kloc = k8 * 8;
            #pragma unroll
            for (int i = 0; i < 8; i++) {
                int bn = warp_n * 64 + i * 8 + fr;
                unsigned b0 = Bsu[(kloc + fc) * BS_LD + bn];
                unsigned b1 = Bsu[(kloc + fc + 4) * BS_LD + bn];
                mma_tf32(acc[i][0], acc[i][1], acc[i][2], acc[i][3],
                         a0, a1, a2, a3, b0, b1);
            }
        }
    }

    int crow = row0 + warp_m * 16 + fr;
    #pragma unroll
    for (int i = 0; i < 8; i++) {
        int col = warp_n * 64 + i * 8 + 2 * fc;
        float2 bv = *(const float2*)(bias + col);
        if (crow < N_NODES) {
            float2 v0;
            v0.x = fmaxf(acc[i][0] + bv.x, 0.f);
            v0.y = fmaxf(acc[i][1] + bv.y, 0.f);
            *(float2*)(out + (size_t)crow * 128 + col) = v0;
        }
        if (crow + 8 < N_NODES) {
            float2 v1;
            v1.x = fmaxf(acc[i][2] + bv.x, 0.f);
            v1.y = fmaxf(acc[i][3] + bv.y, 0.f);
            *(float2*)(out + (size_t)(crow + 8) * 128 + col) = v1;
        }
    }
}

// ---------------- layer-3 TF32 body: C[128 x 64] = X[128 x 128] @ W[128 x 64] ----
// CTA: BM=128, 256 threads = 8 warps ALL along M (16 rows each); BN=64 full width
// per warp (8 n-tiles) so each 4-lane quad owns complete output rows.
// As stride 132 (=4 mod 32): A-frag bank = 4fr+fc distinct. Bs stride 72 (=8 mod 32):
// B-frag bank = 8fc+fr distinct. Single K=128 phase (both tiles fully resident).
#define A3_LD 132
#define B3_LD 72
__device__ __forceinline__ void gemm3_tf32_body(
        const float* __restrict__ X, const float* __restrict__ W,
        float (&acc)[8][4], float* As, float* Bs, int row0) {
    int tid = threadIdx.x;
    int lane = tid & 31;
    int warp_m = tid >> 5;
    int fr = lane >> 2;
    int fc = lane & 3;

    // A tile: 128 rows x 128 cols = 4096 float4, 16 per thread.
    #pragma unroll
    for (int i = 0; i < 16; i++) {
        int idx = tid + i * 256;
        int r = idx >> 5;
        int c4 = idx & 31;
        int gr = row0 + r;
        float4 vv = make_float4(0.f, 0.f, 0.f, 0.f);
        if (gr < N_NODES) vv = ((const float4*)(X + (size_t)gr * 128))[c4];
        unsigned* dstp = (unsigned*)(As + r * A3_LD + c4 * 4);
        dstp[0] = f2tf32(vv.x); dstp[1] = f2tf32(vv.y);
        dstp[2] = f2tf32(vv.z); dstp[3] = f2tf32(vv.w);
    }
    // B tile: 128 rows x 64 cols = 2048 float4, 8 per thread.
    #pragma unroll
    for (int i = 0; i < 8; i++) {
        int idx = tid + i * 256;
        int k = idx >> 4;
        int c4 = idx & 15;
        float4 vv = ((const float4*)(W + (size_t)k * 64))[c4];
        unsigned* dstp = (unsigned*)(Bs + k * B3_LD + c4 * 4);
        dstp[0] = f2tf32(vv.x); dstp[1] = f2tf32(vv.y);
        dstp[2] = f2tf32(vv.z); dstp[3] = f2tf32(vv.w);
    }
    __syncthreads();

    const unsigned* Asu = (const unsigned*)As;
    const unsigned* Bsu = (const unsigned*)Bs;
    int arow = warp_m * 16 + fr;
    #pragma unroll
    for (int k8 = 0; k8 < 16; k8++) {
        int kk = k8 * 8;
        unsigned a0 = Asu[arow * A3_LD + kk + fc];
        unsigned a1 = Asu[(arow + 8) * A3_LD + kk + fc];
        unsigned a2 = Asu[arow * A3_LD + kk + fc + 4];
        unsigned a3 = Asu[(arow + 8) * A3_LD + kk + fc + 4];
        #pragma unroll
        for (int i = 0; i < 8; i++) {
            int bn = i * 8 + fr;
            unsigned b0 = Bsu[(kk + fc) * B3_LD + bn];
            unsigned b1 = Bsu[(kk + fc + 4) * B3_LD + bn];
            mma_tf32(acc[i][0], acc[i][1], acc[i][2], acc[i][3],
                     a0, a1, a2, a3, b0, b1);
        }
    }
}

// layer-3 neighbor GEMM: hn3 = h2 @ Wn3p  (N x 64)
__global__ void __launch_bounds__(256) gemm_n3_kernel(
        const float* __restrict__ X, const float* __restrict__ W,
        float* __restrict__ out) {
    extern __shared__ float smem[];
    float* As = smem;
    float* Bs = smem + 128 * A3_LD;
    int row0 = blockIdx.x * 128;
    int lane = threadIdx.x & 31;
    int warp_m = threadIdx.x >> 5;
    int fr = lane >> 2, fc = lane & 3;
    float acc[8][4];
    #pragma unroll
    for (int i = 0; i < 8; i++)
        #pragma unroll
        for (int j = 0; j < 4; j++) acc[i][j] = 0.f;
    gemm3_tf32_body(X, W, acc, As, Bs, row0);

    int crow = row0 + warp_m * 16 + fr;
    #pragma unroll
    for (int i = 0; i < 8; i++) {
        int col = i * 8 + 2 * fc;
        if (crow < N_NODES)
            *(float2*)(out + (size_t)crow * 64 + col) = make_float2(acc[i][0], acc[i][1]);
        if (crow + 8 < N_NODES)
            *(float2*)(out + (size_t)(crow + 8) * 64 + col) = make_float2(acc[i][2], acc[i][3]);
    }
}

// layer-3 self GEMM + agg + bias + fused log_softmax -> out (N x 40).
// Each 4-lane quad (same fr) holds full rows crow and crow+8; reduce with
// shfl_xor 1,2. Valid cols: i*8+2fc < 40  <=>  i <= 4.
__global__ void __launch_bounds__(256) gemm_s3_lsm_kernel(
        const float* __restrict__ X, const float* __restrict__ W,
        const float* __restrict__ Agg, const float* __restrict__ bias,
        float* __restrict__ out) {
    extern __shared__ float smem[];
    float* As = smem;
    float* Bs = smem + 128 * A3_LD;
    int row0 = blockIdx.x * 128;
    int lane = threadIdx.x & 31;
    int warp_m = threadIdx.x >> 5;
    int fr = lane >> 2, fc = lane & 3;
    float acc[8][4];
    #pragma unroll
    for (int i = 0; i < 8; i++)
        #pragma unroll
        for (int j = 0; j < 4; j++) acc[i][j] = 0.f;
    gemm3_tf32_body(X, W, acc, As, Bs, row0);

    int crow = row0 + warp_m * 16 + fr;
    bool r0ok = crow < N_NODES;
    bool r1ok = crow + 8 < N_NODES;

    float v0[5][2], v1[5][2];
    float mx0 = -CUDART_INF_F, mx1 = -CUDART_INF_F;
    #pragma unroll
    for (int i = 0; i < 5; i++) {
        int col = i * 8 + 2 * fc;
        float2 bv = *(const float2*)(bias + col);
        float2 a0 = r0ok ? *(const float2*)(Agg + (size_t)crow * 64 + col)
                         : make_float2(0.f, 0.f);
        float2 a1 = r1ok ? *(const float2*)(Agg + (size_t)(crow + 8) * 64 + col)
                         : make_float2(0.f, 0.f);
        v0[i][0] = acc[i][0] + a0.x + bv.x;
        v0[i][1] = acc[i][1] + a0.y + bv.y;
        v1[i][0] = acc[i][2] + a1.x + bv.x;
        v1[i][1] = acc[i][3] + a1.y + bv.y;
        mx0 = fmaxf(mx0, fmaxf(v0[i][0], v0[i][1]));
        mx1 = fmaxf(mx1, fmaxf(v1[i][0], v1[i][1]));
    }
    // quad-wide reductions (lanes fr*4 .. fr*4+3)
    mx0 = fmaxf(mx0, __shfl_xor_sync(0xffffffffu, mx0, 1));
    mx0 = fmaxf(mx0, __shfl_xor_sync(0xffffffffu, mx0, 2));
    mx1 = fmaxf(mx1, __shfl_xor_sync(0xffffffffu, mx1, 1));
    mx1 = fmaxf(mx1, __shfl_xor_sync(0xffffffffu, mx1, 2));
    float e0 = 0.f, e1 = 0.f;
    #pragma unroll
    for (int i = 0; i < 5; i++) {
        e0 += __expf(v0[i][0] - mx0) + __expf(v0[i][1] - mx0);
        e1 += __expf(v1[i][0] - mx1) + __expf(v1[i][1] - mx1);
    }
    e0 += __shfl_xor_sync(0xffffffffu, e0, 1);
    e0 += __shfl_xor_sync(0xffffffffu, e0, 2);
    e1 += __shfl_xor_sync(0xffffffffu, e1, 1);
    e1 += __shfl_xor_sync(0xffffffffu, e1, 2);
    float ls0 = mx0 + __logf(e0);
    float ls1 = mx1 + __logf(e1);

    #pragma unroll
    for (int i = 0; i < 5; i++) {
        int col = i * 8 + 2 * fc;
        if (r0ok)
            *(float2*)(out + (size_t)crow * F_OUT + col) =
                make_float2(v0[i][0] - ls0, v0[i][1] - ls0);
        if (r1ok)
            *(float2*)(out + (size_t)(crow + 8) * F_OUT + col) =
                make_float2(v1[i][0] - ls1, v1[i][1] - ls1);
    }
}

// ---------------- host launcher ----------------
extern "C" void kernel_launch(void* const* d_in, const int* in_sizes, int n_in,
                              void* d_out, int out_size) {
    const float* x   = (const float*)d_in[0];
    const int*   ei  = (const int*)d_in[1];
    const float* Ws1 = (const float*)d_in[2];
    const float* Wn1 = (const float*)d_in[3];
    const float* b1  = (const float*)d_in[4];
    const float* Ws2 = (const float*)d_in[5];
    const float* Wn2 = (const float*)d_in[6];
    const float* b2  = (const float*)d_in[7];
    const float* Ws3 = (const float*)d_in[8];
    const float* Wn3 = (const float*)d_in[9];
    const float* b3  = (const float*)d_in[10];
    const float* g1  = (const float*)d_in[11];
    const float* be1 = (const float*)d_in[12];
    const float* m1  = (const float*)d_in[13];
    const float* v1  = (const float*)d_in[14];
    const float* g2  = (const float*)d_in[15];
    const float* be2 = (const float*)d_in[16];
    const float* m2  = (const float*)d_in[17];
    const float* v2  = (const float*)d_in[18];
    float* out = (float*)d_out;

    const int* e_src = ei;
    const int* e_dst = ei + N_EDGES;

    float *p_agg, *p_h, *p_hn3, *p_Wc1, *p_Wc2, *p_Ws3p, *p_Wn3p, *p_bc1, *p_bc2, *p_bc3;
    cudaGetSymbolAddress((void**)&p_agg,  d_agg);
    cudaGetSymbolAddress((void**)&p_h,    d_h);
    cudaGetSymbolAddress((void**)&p_hn3,  d_hn3);
    cudaGetSymbolAddress((void**)&p_Wc1,  d_Wc1);
    cudaGetSymbolAddress((void**)&p_Wc2,  d_Wc2);
    cudaGetSymbolAddress((void**)&p_Ws3p, d_Ws3p);
    cudaGetSymbolAddress((void**)&p_Wn3p, d_Wn3p);
    cudaGetSymbolAddress((void**)&p_bc1,  d_bc1);
    cudaGetSymbolAddress((void**)&p_bc2,  d_bc2);
    cudaGetSymbolAddress((void**)&p_bc3,  d_bc3);

    const int NB_N    = (N_NODES + 255) / 256;        // 391
    const int NB_E    = (N_EDGES + 255) / 256;        // 6250
    const int NB_WARP = (N_NODES * 32 + 255) / 256;   // 12500
    const int NB_G12  = (N_NODES + 63) / 64;          // 1563
    const int NB_G3   = (N_NODES + 127) / 128;        // 782

    const size_t smem_tf32 = (64 * AS_LD + 64 * BS_LD) * sizeof(float);   // ~99 KB
    const size_t smem_g3   = (128 * A3_LD + 128 * B3_LD) * sizeof(float); // ~102 KB
    cudaFuncSetAttribute(gemm_tf32_kernel, cudaFuncAttributeMaxDynamicSharedMemorySize, (int)smem_tf32);
    cudaFuncSetAttribute(gemm_n3_kernel, cudaFuncAttributeMaxDynamicSharedMemorySize, (int)smem_g3);
    cudaFuncSetAttribute(gemm_s3_lsm_kernel, cudaFuncAttributeMaxDynamicSharedMemorySize, (int)smem_g3);

    // CSR build
    zero_deg_kernel<<<NB_N, 256>>>();
    hist_kernel<<<NB_E, 256>>>(e_dst);
    scan_kernel<<<1, 1024>>>();
    copy_cursor_kernel<<<NB_N, 256>>>();
    fill_kernel<<<NB_E, 256>>>(e_src, e_dst);

    // weight prep
    prep_w_kernel<<<(256 * 128 + 255) / 256, 256>>>(Ws1, Wn1, b1, g1, be1, m1, v1, p_Wc1, p_bc1);
    prep_w_kernel<<<(256 * 128 + 255) / 256, 256>>>(Ws2, Wn2, b2, g2, be2, m2, v2, p_Wc2, p_bc2);
    prep_w3_kernel<<<(128 * F_OUT_P + 255) / 256, 256>>>(Ws3, Wn3, b3, p_Ws3p, p_Wn3p, p_bc3);

    // layer 1
    agg_kernel<<<NB_WARP, 256>>>(x, p_agg);
    gemm_tf32_kernel<<<NB_G12, 256, smem_tf32>>>(x, p_agg, p_Wc1, p_bc1, p_h);
    // layer 2 (in place: each block reads/writes only its own rows)
    agg_kernel<<<NB_WARP, 256>>>(p_h, p_agg);
    gemm_tf32_kernel<<<NB_G12, 256, smem_tf32>>>(p_h, p_agg, p_Wc2, p_bc2, p_h);
    // layer 3: neighbor GEMM first (agg linear), 64-wide agg, then fused final
    gemm_n3_kernel<<<NB_G3, 256, smem_g3>>>(p_h, p_Wn3p, p_hn3);
    agg64_kernel<<<NB_WARP, 256>>>(p_hn3, p_agg);
    gemm_s3_lsm_kernel<<<NB_G3, 256, smem_g3>>>(p_h, p_Ws3p, p_agg, p_bc3, out);
}